// round 9
// baseline (speedup 1.0000x reference)
#include <cuda_runtime.h>
#include <cuda_fp16.h>
#include <math.h>
#include <stdint.h>

// FlashAttention fwd, causal, fp32 I/O, fp16 mma.sync (m16n8k16), sm_103.
// B=1, S=4096, H=16, D=64. Layout [s,h,d]: d contiguous, s stride 1024.
//
// Pre-pass converts once: qh = half(q*scale), kh = half(k), vth = half(V^T).
// Main kernel: CTA = (head, 128 q rows), 4 warps x 32 rows (mt=2 amortization),
// BN=64 kv tiles double-buffered via cp.async, processed as two 32-wide halves
// to halve live score registers -> 3 CTAs/SM (12 warps).

constexpr int S_LEN = 4096;
constexpr int H     = 16;
constexpr int Dh    = 64;
constexpr int BM    = 128;
constexpr int BN    = 64;
constexpr int NT    = 128;
constexpr int PH    = 72;        // smem pitch in halves (bank = 4g+tg, clean)

// smem offsets in halves
constexpr int KH_OFF  = 0;                    // 2 x 64x72
constexpr int VTH_OFF = 2 * BN * PH;          // 2 x 64x72
constexpr int PSH_OFF = 4 * BN * PH;          // 128x72 (Q staging / P)
constexpr int SMEM_H  = PSH_OFF + BM * PH;
constexpr int SMEM_BYTES = SMEM_H * 2;        // 55296 B -> 3 CTAs/SM

// one-time converted operands
__device__ __half qh_g[S_LEN * H * Dh];       // [s][h][d], pre-scaled
__device__ __half kh_g[S_LEN * H * Dh];       // [s][h][d]
__device__ __half vth_g[H * Dh * S_LEN];      // [h][d][s]  (V transposed)

__device__ __forceinline__ float ex2(float x) {
    float y;
    asm("ex2.approx.f32 %0, %1;" : "=f"(y) : "f"(x));
    return y;
}
__device__ __forceinline__ void mma16(float* d, const uint32_t* a, const uint32_t* b) {
    asm volatile(
        "mma.sync.aligned.m16n8k16.row.col.f32.f16.f16.f32 "
        "{%0,%1,%2,%3}, {%4,%5,%6,%7}, {%8,%9}, {%0,%1,%2,%3};"
        : "+f"(d[0]), "+f"(d[1]), "+f"(d[2]), "+f"(d[3])
        : "r"(a[0]), "r"(a[1]), "r"(a[2]), "r"(a[3]), "r"(b[0]), "r"(b[1]));
}
__device__ __forceinline__ void cpa16(uint32_t dst, const void* src) {
    asm volatile("cp.async.cg.shared.global [%0], [%1], 16;"
                 :: "r"(dst), "l"(src) : "memory");
}

// ---------------- pre-pass: fp32 -> fp16 (+scale Q, transpose V) ----------
__global__ void __launch_bounds__(128)
cvt_kernel(const float* __restrict__ q, const float* __restrict__ k,
           const float* __restrict__ v)
{
    __shared__ __half vt_s[Dh][72];           // transposed V tile staging
    const int h  = blockIdx.x;
    const int s0 = blockIdx.y * 64;
    const int t  = threadIdx.x;
    const float c = 0.125f * 1.44269504088896340736f;   // D^-0.5 * log2(e)

    #pragma unroll
    for (int i = 0; i < 8; i++) {
        int idx = t + i * 128;                // 0..1023
        int row = idx >> 4, c4 = idx & 15;    // 64 rows x 16 float4-chunks
        size_t g = (size_t)(s0 + row) * (H * Dh) + (size_t)h * Dh + c4 * 4;
        float4 fq = *(const float4*)(q + g);
        float4 fk = *(const float4*)(k + g);
        float4 fv = *(const float4*)(v + g);
        ((__half2*)(qh_g + g))[0] = __floats2half2_rn(fq.x * c, fq.y * c);
        ((__half2*)(qh_g + g))[1] = __floats2half2_rn(fq.z * c, fq.w * c);
        ((__half2*)(kh_g + g))[0] = __floats2half2_rn(fk.x, fk.y);
        ((__half2*)(kh_g + g))[1] = __floats2half2_rn(fk.z, fk.w);
        vt_s[c4 * 4 + 0][row] = __float2half_rn(fv.x);
        vt_s[c4 * 4 + 1][row] = __float2half_rn(fv.y);
        vt_s[c4 * 4 + 2][row] = __float2half_rn(fv.z);
        vt_s[c4 * 4 + 3][row] = __float2half_rn(fv.w);
    }
    __syncthreads();
    #pragma unroll
    for (int i = 0; i < 16; i++) {
        int idx = t + i * 128;                // 0..2047 half2 chunks
        int d = idx >> 5, c2 = idx & 31;
        __half2 val = __halves2half2(vt_s[d][2 * c2], vt_s[d][2 * c2 + 1]);
        *(__half2*)(vth_g + ((size_t)h * Dh + d) * S_LEN + s0 + c2 * 2) = val;
    }
}

// copy one 64x64 K tile + Vt tile (half) -> smem; 4+4 16B chunks per thread
__device__ __forceinline__ void issue_tile(uint32_t kdst, uint32_t vdst,
                                           int k0, int h, int t) {
    #pragma unroll
    for (int i = 0; i < 4; i++) {
        int idx = t + i * NT;                 // 0..511
        int row = idx >> 3, c = idx & 7;      // 64 rows x 8 16B-chunks
        cpa16(kdst + (uint32_t)(row * PH + c * 8) * 2,
              kh_g + (size_t)(k0 + row) * (H * Dh) + (size_t)h * Dh + c * 8);
        cpa16(vdst + (uint32_t)(row * PH + c * 8) * 2,
              vth_g + ((size_t)h * Dh + row) * S_LEN + k0 + c * 8);
    }
    asm volatile("cp.async.commit_group;" ::: "memory");
}

__global__ void __launch_bounds__(NT, 3)
fa_mma_kernel(const int* __restrict__ causal_p, float* __restrict__ out)
{
    extern __shared__ __half smh[];
    uint32_t smb;
    asm("{ .reg .u64 t; cvta.to.shared.u64 t, %1; cvt.u32.u64 %0, t; }"
        : "=r"(smb) : "l"(smh));
    __half* Psh = smh + PSH_OFF;

    const int t    = threadIdx.x;
    const int lane = t & 31;
    const int g    = lane >> 2;
    const int tg   = lane & 3;
    const int h    = blockIdx.x;
    const int qb   = (int)gridDim.y - 1 - (int)blockIdx.y;  // heavy tiles first
    const int causal = *causal_p;
    const int wb   = (t >> 5) * 32;       // warp's 32-row base in CTA tile
    const int q0   = qb * BM;
    const int ktiles = causal ? 2 * (qb + 1) : (S_LEN / BN);

    // ---- stage Q (group 0) and kv tile 0 (group 1)
    #pragma unroll
    for (int i = 0; i < 8; i++) {
        int idx = t + i * NT;                 // 0..1023
        int row = idx >> 3, c = idx & 7;
        cpa16(smb + (uint32_t)(PSH_OFF + row * PH + c * 8) * 2,
              qh_g + (size_t)(q0 + row) * (H * Dh) + (size_t)h * Dh + c * 8);
    }
    asm volatile("cp.async.commit_group;" ::: "memory");
    issue_tile(smb + KH_OFF * 2, smb + VTH_OFF * 2, 0, h, t);

    asm volatile("cp.async.wait_group 1;" ::: "memory");   // Q ready
    __syncthreads();

    // ---- lift Q fragments (m16n8k16 A layout), rows warp-private
    uint32_t qa[2][4][4];                     // [mtile][ktile][frag]
    #pragma unroll
    for (int mt = 0; mt < 2; mt++) {
        int r0 = wb + mt * 16 + g;
        #pragma unroll
        for (int kt = 0; kt < 4; kt++) {
            const __half* p0 = Psh + r0 * PH + kt * 16 + 2 * tg;
            const __half* p1 = Psh + (r0 + 8) * PH + kt * 16 + 2 * tg;
            qa[mt][kt][0] = *(const uint32_t*)p0;
            qa[mt][kt][1] = *(const uint32_t*)p1;
            qa[mt][kt][2] = *(const uint32_t*)(p0 + 8);
            qa[mt][kt][3] = *(const uint32_t*)(p1 + 8);
        }
    }

    float o[2][8][4];
    #pragma unroll
    for (int mt = 0; mt < 2; mt++)
        #pragma unroll
        for (int nt = 0; nt < 8; nt++)
            #pragma unroll
            for (int e = 0; e < 4; e++) o[mt][nt][e] = 0.0f;
    float mrow[4] = {-INFINITY, -INFINITY, -INFINITY, -INFINITY};
    float lrow[4] = {0.0f, 0.0f, 0.0f, 0.0f};

    for (int kb = 0; kb < ktiles; kb++) {
        const int k0 = kb * BN;
        const int cur = kb & 1;
        const __half* Kh = smh + KH_OFF + cur * (BN * PH);
        const __half* Vh = smh + VTH_OFF + cur * (BN * PH);

        __syncthreads();   // prev iter's reads of buffer cur^1 / Psh done
        if (kb + 1 < ktiles)
            issue_tile(smb + (KH_OFF + (cur ^ 1) * BN * PH) * 2,
                       smb + (VTH_OFF + (cur ^ 1) * BN * PH) * 2,
                       k0 + BN, h, t);
        else
            asm volatile("cp.async.commit_group;" ::: "memory");
        asm volatile("cp.async.wait_group 1;" ::: "memory");
        __syncthreads();   // tile kb visible CTA-wide

        // ==== process the 64-wide tile as two 32-wide halves ====
        #pragma unroll
        for (int nh = 0; nh < 2; nh++) {
            const int cbase = nh * 32;        // kv col base within tile

            // ---- MMA1 half: S[32 x 32] = Q @ K^T
            float s[2][4][4];
            #pragma unroll
            for (int mt = 0; mt < 2; mt++)
                #pragma unroll
                for (int nt = 0; nt < 4; nt++)
                    #pragma unroll
                    for (int e = 0; e < 4; e++) s[mt][nt][e] = 0.0f;
            #pragma unroll
            for (int kt = 0; kt < 4; kt++) {
                #pragma unroll
                for (int nt = 0; nt < 4; nt++) {
                    const __half* kp =
                        Kh + (cbase + nt * 8 + g) * PH + kt * 16 + 2 * tg;
                    uint32_t b[2];
                    b[0] = *(const uint32_t*)kp;
                    b[1] = *(const uint32_t*)(kp + 8);
                    mma16(s[0][nt], qa[0][kt], b);
                    mma16(s[1][nt], qa[1][kt], b);
                }
            }

            // ---- causal mask (diagonal tiles only)
            if (causal && kb >= 2 * qb) {
                #pragma unroll
                for (int mt = 0; mt < 2; mt++) {
                    int r0 = q0 + wb + mt * 16 + g;
                    #pragma unroll
                    for (int nt = 0; nt < 4; nt++) {
                        int col = k0 + cbase + nt * 8 + 2 * tg;
                        if (col     > r0)     s[mt][nt][0] = -INFINITY;
                        if (col + 1 > r0)     s[mt][nt][1] = -INFINITY;
                        if (col     > r0 + 8) s[mt][nt][2] = -INFINITY;
                        if (col + 1 > r0 + 8) s[mt][nt][3] = -INFINITY;
                    }
                }
            }

            // ---- online softmax (4 rows/thread; quad owns a row)
            #pragma unroll
            for (int mt = 0; mt < 2; mt++) {
                #pragma unroll
                for (int hi = 0; hi < 2; hi++) {
                    const int ri = mt * 2 + hi;
                    float tm = -INFINITY;
                    #pragma unroll
                    for (int nt = 0; nt < 4; nt++)
                        tm = fmaxf(tm, fmaxf(s[mt][nt][hi * 2],
                                             s[mt][nt][hi * 2 + 1]));
                    tm = fmaxf(tm, __shfl_xor_sync(0xffffffffu, tm, 1));
                    tm = fmaxf(tm, __shfl_xor_sync(0xffffffffu, tm, 2));
                    float nm   = fmaxf(mrow[ri], tm);
                    float corr = ex2(mrow[ri] - nm);   // first tile: -inf -> 0
                    mrow[ri] = nm;
                    float ls = 0.0f;
                    #pragma unroll
                    for (int nt = 0; nt < 4; nt++) {
                        float e0 = ex2(s[mt][nt][hi * 2]     - nm);
                        float e1 = ex2(s[mt][nt][hi * 2 + 1] - nm);
                        s[mt][nt][hi * 2]     = e0;
                        s[mt][nt][hi * 2 + 1] = e1;
                        ls += e0 + e1;
                    }
                    #pragma unroll
                    for (int nt = 0; nt < 8; nt++) {
                        o[mt][nt][hi * 2]     *= corr;
                        o[mt][nt][hi * 2 + 1] *= corr;
                    }
                    lrow[ri] = lrow[ri] * corr + ls;
                }
            }

            // ---- P half (rn half2) -> Psh; rows warp-private
            #pragma unroll
            for (int mt = 0; mt < 2; mt++) {
                int r0 = wb + mt * 16 + g;
                #pragma unroll
                for (int nt = 0; nt < 4; nt++) {
                    *(__half2*)(Psh + r0 * PH + cbase + nt * 8 + 2 * tg) =
                        __floats2half2_rn(s[mt][nt][0], s[mt][nt][1]);
                    *(__half2*)(Psh + (r0 + 8) * PH + cbase + nt * 8 + 2 * tg) =
                        __floats2half2_rn(s[mt][nt][2], s[mt][nt][3]);
                }
            }
            __syncwarp();

            // ---- MMA2 half: O += P[32x32] @ V[32x64]  (2 k-steps of 16)
            #pragma unroll
            for (int kt = 0; kt < 2; kt++) {
                uint32_t pa[2][4];
                #pragma unroll
                for (int mt = 0; mt < 2; mt++) {
                    int r0 = wb + mt * 16 + g;
                    const __half* p0 = Psh + r0 * PH + cbase + kt * 16 + 2 * tg;
                    const __half* p1 = Psh + (r0 + 8) * PH + cbase + kt * 16 + 2 * tg;
                    pa[mt][0] = *(const uint32_t*)p0;
                    pa[mt][1] = *(const uint32_t*)p1;
                    pa[mt][2] = *(const uint32_t*)(p0 + 8);
                    pa[mt][3] = *(const uint32_t*)(p1 + 8);
                }
                #pragma unroll
                for (int nt = 0; nt < 8; nt++) {
                    const __half* vp =
                        Vh + (nt * 8 + g) * PH + cbase + kt * 16 + 2 * tg;
                    uint32_t b[2];
                    b[0] = *(const uint32_t*)vp;
                    b[1] = *(const uint32_t*)(vp + 8);
                    mma16(o[0][nt], pa[0], b);
                    mma16(o[1][nt], pa[1], b);
                }
            }
        }
    }

    // ---- finalize: row-sum across quad, normalize, store
    #pragma unroll
    for (int ri = 0; ri < 4; ri++) {
        lrow[ri] += __shfl_xor_sync(0xffffffffu, lrow[ri], 1);
        lrow[ri] += __shfl_xor_sync(0xffffffffu, lrow[ri], 2);
    }
    #pragma unroll
    for (int mt = 0; mt < 2; mt++) {
        #pragma unroll
        for (int hi = 0; hi < 2; hi++) {
            const int ri = mt * 2 + hi;
            const float inv = 1.0f / lrow[ri];
            const int rg = q0 + wb + mt * 16 + g + hi * 8;
            float* op = out + (size_t)rg * (H * Dh) + (size_t)h * Dh;
            #pragma unroll
            for (int nt = 0; nt < 8; nt++) {
                float2 f2;
                f2.x = o[mt][nt][hi * 2]     * inv;
                f2.y = o[mt][nt][hi * 2 + 1] * inv;
                *(float2*)(op + nt * 8 + 2 * tg) = f2;
            }
        }
    }
}

extern "C" void kernel_launch(void* const* d_in, const int* in_sizes, int n_in,
                              void* d_out, int out_size)
{
    const float* q = (const float*)d_in[0];
    const float* k = (const float*)d_in[1];
    const float* v = (const float*)d_in[2];
    const int* causal = (const int*)d_in[3];
    float* out = (float*)d_out;

    dim3 cgrid(H, S_LEN / 64);   // (16, 64)
    cvt_kernel<<<cgrid, 128>>>(q, k, v);

    cudaFuncSetAttribute(fa_mma_kernel,
                         cudaFuncAttributeMaxDynamicSharedMemorySize, SMEM_BYTES);
    dim3 grid(H, S_LEN / BM);    // (16, 32)
    fa_mma_kernel<<<grid, NT, SMEM_BYTES>>>(causal, out);
}

// round 10
// speedup vs baseline: 1.4590x; 1.4590x over previous
#include <cuda_runtime.h>
#include <cuda_fp16.h>
#include <math.h>
#include <stdint.h>

// FlashAttention fwd, causal, fp32 I/O, fp16 mma.sync (m16n8k16), sm_103.
// B=1, S=4096, H=16, D=64. Layout [s,h,d]: d contiguous, s stride 1024.
//
// Pre-pass converts once: qh = half(q*scale), kh = half(k), vth = half(V^T).
// Main kernel: CTA = (head, 128 q rows), 4 warps x 32 rows, BN=64 kv tiles
// double-buffered via cp.async. P is kept in REGISTERS between MMA1 and MMA2
// (m16n8k16 C-fragment == A-fragment layout), no smem round-trip.

constexpr int S_LEN = 4096;
constexpr int H     = 16;
constexpr int Dh    = 64;
constexpr int BM    = 128;
constexpr int BN    = 64;
constexpr int NT    = 128;
constexpr int PH    = 72;        // smem pitch in halves (bank = 4g+tg, clean)

// smem offsets in halves
constexpr int KH_OFF  = 0;                    // 2 x 64x72
constexpr int VTH_OFF = 2 * BN * PH;          // 2 x 64x72
constexpr int PSH_OFF = 4 * BN * PH;          // 128x72 (Q staging only)
constexpr int SMEM_H  = PSH_OFF + BM * PH;
constexpr int SMEM_BYTES = SMEM_H * 2;        // 55296 B -> 2 CTAs/SM

// one-time converted operands
__device__ __half qh_g[S_LEN * H * Dh];       // [s][h][d], pre-scaled
__device__ __half kh_g[S_LEN * H * Dh];       // [s][h][d]
__device__ __half vth_g[H * Dh * S_LEN];      // [h][d][s]  (V transposed)

__device__ __forceinline__ float ex2(float x) {
    float y;
    asm("ex2.approx.f32 %0, %1;" : "=f"(y) : "f"(x));
    return y;
}
__device__ __forceinline__ void mma16(float* d, const uint32_t* a, const uint32_t* b) {
    asm volatile(
        "mma.sync.aligned.m16n8k16.row.col.f32.f16.f16.f32 "
        "{%0,%1,%2,%3}, {%4,%5,%6,%7}, {%8,%9}, {%0,%1,%2,%3};"
        : "+f"(d[0]), "+f"(d[1]), "+f"(d[2]), "+f"(d[3])
        : "r"(a[0]), "r"(a[1]), "r"(a[2]), "r"(a[3]), "r"(b[0]), "r"(b[1]));
}
__device__ __forceinline__ void cpa16(uint32_t dst, const void* src) {
    asm volatile("cp.async.cg.shared.global [%0], [%1], 16;"
                 :: "r"(dst), "l"(src) : "memory");
}
__device__ __forceinline__ uint32_t h2(float a, float b) {
    __half2 v = __floats2half2_rn(a, b);
    return *(uint32_t*)&v;
}

// ---------------- pre-pass: fp32 -> fp16 (+scale Q, transpose V) ----------
__global__ void __launch_bounds__(128)
cvt_kernel(const float* __restrict__ q, const float* __restrict__ k,
           const float* __restrict__ v)
{
    __shared__ __half vt_s[Dh][72];           // transposed V tile staging
    const int h  = blockIdx.x;
    const int s0 = blockIdx.y * 64;
    const int t  = threadIdx.x;
    const float c = 0.125f * 1.44269504088896340736f;   // D^-0.5 * log2(e)

    #pragma unroll
    for (int i = 0; i < 8; i++) {
        int idx = t + i * 128;                // 0..1023
        int row = idx >> 4, c4 = idx & 15;    // 64 rows x 16 float4-chunks
        size_t g = (size_t)(s0 + row) * (H * Dh) + (size_t)h * Dh + c4 * 4;
        float4 fq = *(const float4*)(q + g);
        float4 fk = *(const float4*)(k + g);
        float4 fv = *(const float4*)(v + g);
        ((__half2*)(qh_g + g))[0] = __floats2half2_rn(fq.x * c, fq.y * c);
        ((__half2*)(qh_g + g))[1] = __floats2half2_rn(fq.z * c, fq.w * c);
        ((__half2*)(kh_g + g))[0] = __floats2half2_rn(fk.x, fk.y);
        ((__half2*)(kh_g + g))[1] = __floats2half2_rn(fk.z, fk.w);
        vt_s[c4 * 4 + 0][row] = __float2half_rn(fv.x);
        vt_s[c4 * 4 + 1][row] = __float2half_rn(fv.y);
        vt_s[c4 * 4 + 2][row] = __float2half_rn(fv.z);
        vt_s[c4 * 4 + 3][row] = __float2half_rn(fv.w);
    }
    __syncthreads();
    #pragma unroll
    for (int i = 0; i < 16; i++) {
        int idx = t + i * 128;                // 0..2047 half2 chunks
        int d = idx >> 5, c2 = idx & 31;
        __half2 val = __halves2half2(vt_s[d][2 * c2], vt_s[d][2 * c2 + 1]);
        *(__half2*)(vth_g + ((size_t)h * Dh + d) * S_LEN + s0 + c2 * 2) = val;
    }
}

// copy one 64x64 K tile + Vt tile (half) -> smem; 4+4 16B chunks per thread
__device__ __forceinline__ void issue_tile(uint32_t kdst, uint32_t vdst,
                                           int k0, int h, int t) {
    #pragma unroll
    for (int i = 0; i < 4; i++) {
        int idx = t + i * NT;                 // 0..511
        int row = idx >> 3, c = idx & 7;      // 64 rows x 8 16B-chunks
        cpa16(kdst + (uint32_t)(row * PH + c * 8) * 2,
              kh_g + (size_t)(k0 + row) * (H * Dh) + (size_t)h * Dh + c * 8);
        cpa16(vdst + (uint32_t)(row * PH + c * 8) * 2,
              vth_g + ((size_t)h * Dh + row) * S_LEN + k0 + c * 8);
    }
    asm volatile("cp.async.commit_group;" ::: "memory");
}

__global__ void __launch_bounds__(NT, 2)
fa_mma_kernel(const int* __restrict__ causal_p, float* __restrict__ out)
{
    extern __shared__ __half smh[];
    uint32_t smb;
    asm("{ .reg .u64 t; cvta.to.shared.u64 t, %1; cvt.u32.u64 %0, t; }"
        : "=r"(smb) : "l"(smh));
    __half* Psh = smh + PSH_OFF;

    const int t    = threadIdx.x;
    const int lane = t & 31;
    const int g    = lane >> 2;
    const int tg   = lane & 3;
    const int h    = blockIdx.x;
    const int qb   = (int)gridDim.y - 1 - (int)blockIdx.y;  // heavy tiles first
    const int causal = *causal_p;
    const int wb   = (t >> 5) * 32;       // warp's 32-row base in CTA tile
    const int q0   = qb * BM;
    const int ktiles = causal ? 2 * (qb + 1) : (S_LEN / BN);

    // ---- stage Q (group 0) and kv tile 0 (group 1)
    #pragma unroll
    for (int i = 0; i < 8; i++) {
        int idx = t + i * NT;                 // 0..1023
        int row = idx >> 3, c = idx & 7;
        cpa16(smb + (uint32_t)(PSH_OFF + row * PH + c * 8) * 2,
              qh_g + (size_t)(q0 + row) * (H * Dh) + (size_t)h * Dh + c * 8);
    }
    asm volatile("cp.async.commit_group;" ::: "memory");
    issue_tile(smb + KH_OFF * 2, smb + VTH_OFF * 2, 0, h, t);

    asm volatile("cp.async.wait_group 1;" ::: "memory");   // Q ready
    __syncthreads();

    // ---- lift Q fragments (m16n8k16 A layout), rows warp-private
    uint32_t qa[2][4][4];                     // [mtile][ktile][frag]
    #pragma unroll
    for (int mt = 0; mt < 2; mt++) {
        int r0 = wb + mt * 16 + g;
        #pragma unroll
        for (int kt = 0; kt < 4; kt++) {
            const __half* p0 = Psh + r0 * PH + kt * 16 + 2 * tg;
            const __half* p1 = Psh + (r0 + 8) * PH + kt * 16 + 2 * tg;
            qa[mt][kt][0] = *(const uint32_t*)p0;
            qa[mt][kt][1] = *(const uint32_t*)p1;
            qa[mt][kt][2] = *(const uint32_t*)(p0 + 8);
            qa[mt][kt][3] = *(const uint32_t*)(p1 + 8);
        }
    }

    float o[2][8][4];
    #pragma unroll
    for (int mt = 0; mt < 2; mt++)
        #pragma unroll
        for (int nt = 0; nt < 8; nt++)
            #pragma unroll
            for (int e = 0; e < 4; e++) o[mt][nt][e] = 0.0f;
    float mrow[4] = {-INFINITY, -INFINITY, -INFINITY, -INFINITY};
    float lrow[4] = {0.0f, 0.0f, 0.0f, 0.0f};

    for (int kb = 0; kb < ktiles; kb++) {
        const int k0 = kb * BN;
        const int cur = kb & 1;
        const __half* Kh = smh + KH_OFF + cur * (BN * PH);
        const __half* Vh = smh + VTH_OFF + cur * (BN * PH);

        __syncthreads();   // prev iter's reads of buffer cur^1 done
        if (kb + 1 < ktiles)
            issue_tile(smb + (KH_OFF + (cur ^ 1) * BN * PH) * 2,
                       smb + (VTH_OFF + (cur ^ 1) * BN * PH) * 2,
                       k0 + BN, h, t);
        else
            asm volatile("cp.async.commit_group;" ::: "memory");
        asm volatile("cp.async.wait_group 1;" ::: "memory");
        __syncthreads();   // tile kb visible CTA-wide

        // ---- MMA1: S[32 x 64] = Q @ K^T (4 k-steps of 16)
        float s[2][8][4];
        #pragma unroll
        for (int mt = 0; mt < 2; mt++)
            #pragma unroll
            for (int nt = 0; nt < 8; nt++)
                #pragma unroll
                for (int e = 0; e < 4; e++) s[mt][nt][e] = 0.0f;
        #pragma unroll
        for (int kt = 0; kt < 4; kt++) {
            #pragma unroll
            for (int nt = 0; nt < 8; nt++) {
                const __half* kp = Kh + (nt * 8 + g) * PH + kt * 16 + 2 * tg;
                uint32_t b[2];
                b[0] = *(const uint32_t*)kp;
                b[1] = *(const uint32_t*)(kp + 8);
                mma16(s[0][nt], qa[0][kt], b);
                mma16(s[1][nt], qa[1][kt], b);
            }
        }

        // ---- causal mask (diagonal tiles only)
        if (causal && kb >= 2 * qb) {
            #pragma unroll
            for (int mt = 0; mt < 2; mt++) {
                int r0 = q0 + wb + mt * 16 + g;
                #pragma unroll
                for (int nt = 0; nt < 8; nt++) {
                    int col = k0 + nt * 8 + 2 * tg;
                    if (col     > r0)     s[mt][nt][0] = -INFINITY;
                    if (col + 1 > r0)     s[mt][nt][1] = -INFINITY;
                    if (col     > r0 + 8) s[mt][nt][2] = -INFINITY;
                    if (col + 1 > r0 + 8) s[mt][nt][3] = -INFINITY;
                }
            }
        }

        // ---- online softmax (4 rows/thread; quad owns a row)
        #pragma unroll
        for (int mt = 0; mt < 2; mt++) {
            #pragma unroll
            for (int hi = 0; hi < 2; hi++) {
                const int ri = mt * 2 + hi;
                float tm = -INFINITY;
                #pragma unroll
                for (int nt = 0; nt < 8; nt++)
                    tm = fmaxf(tm, fmaxf(s[mt][nt][hi * 2], s[mt][nt][hi * 2 + 1]));
                tm = fmaxf(tm, __shfl_xor_sync(0xffffffffu, tm, 1));
                tm = fmaxf(tm, __shfl_xor_sync(0xffffffffu, tm, 2));
                float nm   = fmaxf(mrow[ri], tm);
                float corr = ex2(mrow[ri] - nm);     // first tile: -inf -> 0
                mrow[ri] = nm;
                float ls = 0.0f;
                #pragma unroll
                for (int nt = 0; nt < 8; nt++) {
                    float e0 = ex2(s[mt][nt][hi * 2]     - nm);
                    float e1 = ex2(s[mt][nt][hi * 2 + 1] - nm);
                    s[mt][nt][hi * 2]     = e0;
                    s[mt][nt][hi * 2 + 1] = e1;
                    ls += e0 + e1;
                    o[mt][nt][hi * 2]     *= corr;
                    o[mt][nt][hi * 2 + 1] *= corr;
                }
                lrow[ri] = lrow[ri] * corr + ls;
            }
        }

        // ---- MMA2: O += P[32x64] @ V[64x64], P straight from registers.
        // m16n8k16 C-fragment layout == A-fragment layout:
        //   pa = { h2(s[2kt][0],s[2kt][1]), h2(s[2kt][2],s[2kt][3]),
        //          h2(s[2kt+1][0],[1]),     h2(s[2kt+1][2],[3]) }
        #pragma unroll
        for (int kt = 0; kt < 4; kt++) {
            uint32_t pa[2][4];
            #pragma unroll
            for (int mt = 0; mt < 2; mt++) {
                pa[mt][0] = h2(s[mt][2 * kt][0],     s[mt][2 * kt][1]);
                pa[mt][1] = h2(s[mt][2 * kt][2],     s[mt][2 * kt][3]);
                pa[mt][2] = h2(s[mt][2 * kt + 1][0], s[mt][2 * kt + 1][1]);
                pa[mt][3] = h2(s[mt][2 * kt + 1][2], s[mt][2 * kt + 1][3]);
            }
            #pragma unroll
            for (int nt = 0; nt < 8; nt++) {
                const __half* vp = Vh + (nt * 8 + g) * PH + kt * 16 + 2 * tg;
                uint32_t b[2];
                b[0] = *(const uint32_t*)vp;
                b[1] = *(const uint32_t*)(vp + 8);
                mma16(o[0][nt], pa[0], b);
                mma16(o[1][nt], pa[1], b);
            }
        }
    }

    // ---- finalize: row-sum across quad, normalize, store
    #pragma unroll
    for (int ri = 0; ri < 4; ri++) {
        lrow[ri] += __shfl_xor_sync(0xffffffffu, lrow[ri], 1);
        lrow[ri] += __shfl_xor_sync(0xffffffffu, lrow[ri], 2);
    }
    #pragma unroll
    for (int mt = 0; mt < 2; mt++) {
        #pragma unroll
        for (int hi = 0; hi < 2; hi++) {
            const int ri = mt * 2 + hi;
            const float inv = 1.0f / lrow[ri];
            const int rg = q0 + wb + mt * 16 + g + hi * 8;
            float* op = out + (size_t)rg * (H * Dh) + (size_t)h * Dh;
            #pragma unroll
            for (int nt = 0; nt < 8; nt++) {
                float2 f2;
                f2.x = o[mt][nt][hi * 2]     * inv;
                f2.y = o[mt][nt][hi * 2 + 1] * inv;
                *(float2*)(op + nt * 8 + 2 * tg) = f2;
            }
        }
    }
}

extern "C" void kernel_launch(void* const* d_in, const int* in_sizes, int n_in,
                              void* d_out, int out_size)
{
    const float* q = (const float*)d_in[0];
    const float* k = (const float*)d_in[1];
    const float* v = (const float*)d_in[2];
    const int* causal = (const int*)d_in[3];
    float* out = (float*)d_out;

    dim3 cgrid(H, S_LEN / 64);   // (16, 64)
    cvt_kernel<<<cgrid, 128>>>(q, k, v);

    cudaFuncSetAttribute(fa_mma_kernel,
                         cudaFuncAttributeMaxDynamicSharedMemorySize, SMEM_BYTES);
    dim3 grid(H, S_LEN / BM);    // (16, 32)
    fa_mma_kernel<<<grid, NT, SMEM_BYTES>>>(causal, out);
}

// round 11
// speedup vs baseline: 1.5832x; 1.0852x over previous
#include <cuda_runtime.h>
#include <cuda_fp16.h>
#include <math.h>
#include <stdint.h>

// FlashAttention fwd, causal, fp32 I/O, fp16 mma.sync (m16n8k16), sm_103.
// B=1, S=4096, H=16, D=64. Layout [s,h,d]: d contiguous, s stride 1024.
//
// Pre-pass converts once: qh = half(q*scale), kh = half(k), vth = half(V^T).
// Main kernel: CTA = (head, 128 q rows), 4 warps x 32 rows, BN=64 kv tiles
// double-buffered via cp.async. P stays in registers between MMA1 and MMA2.
// K/V B-fragments loaded with ldmatrix.m8n8.x4 (4 fragments per instruction).

constexpr int S_LEN = 4096;
constexpr int H     = 16;
constexpr int Dh    = 64;
constexpr int BM    = 128;
constexpr int BN    = 64;
constexpr int NT    = 128;
constexpr int PH    = 72;        // smem pitch in halves; ldmatrix rows hit
                                 // banks 4r+c (stride 36 b32) -> conflict-free

// smem offsets in halves
constexpr int KH_OFF  = 0;                    // 2 x 64x72
constexpr int VTH_OFF = 2 * BN * PH;          // 2 x 64x72
constexpr int PSH_OFF = 4 * BN * PH;          // 128x72 (Q staging only)
constexpr int SMEM_H  = PSH_OFF + BM * PH;
constexpr int SMEM_BYTES = SMEM_H * 2;        // 55296 B -> 2 CTAs/SM

// one-time converted operands
__device__ __half qh_g[S_LEN * H * Dh];       // [s][h][d], pre-scaled
__device__ __half kh_g[S_LEN * H * Dh];       // [s][h][d]
__device__ __half vth_g[H * Dh * S_LEN];      // [h][d][s]  (V transposed)

__device__ __forceinline__ float ex2(float x) {
    float y;
    asm("ex2.approx.f32 %0, %1;" : "=f"(y) : "f"(x));
    return y;
}
__device__ __forceinline__ void mma16(float* d, const uint32_t* a,
                                      uint32_t b0, uint32_t b1) {
    asm volatile(
        "mma.sync.aligned.m16n8k16.row.col.f32.f16.f16.f32 "
        "{%0,%1,%2,%3}, {%4,%5,%6,%7}, {%8,%9}, {%0,%1,%2,%3};"
        : "+f"(d[0]), "+f"(d[1]), "+f"(d[2]), "+f"(d[3])
        : "r"(a[0]), "r"(a[1]), "r"(a[2]), "r"(a[3]), "r"(b0), "r"(b1));
}
__device__ __forceinline__ void ldsm4(uint32_t& r0, uint32_t& r1,
                                      uint32_t& r2, uint32_t& r3, uint32_t a) {
    asm volatile("ldmatrix.sync.aligned.m8n8.x4.shared.b16 {%0,%1,%2,%3}, [%4];"
                 : "=r"(r0), "=r"(r1), "=r"(r2), "=r"(r3) : "r"(a));
}
__device__ __forceinline__ void cpa16(uint32_t dst, const void* src) {
    asm volatile("cp.async.cg.shared.global [%0], [%1], 16;"
                 :: "r"(dst), "l"(src) : "memory");
}
__device__ __forceinline__ uint32_t h2(float a, float b) {
    __half2 v = __floats2half2_rn(a, b);
    return *(uint32_t*)&v;
}

// ---------------- pre-pass: fp32 -> fp16 (+scale Q, transpose V) ----------
__global__ void __launch_bounds__(128)
cvt_kernel(const float* __restrict__ q, const float* __restrict__ k,
           const float* __restrict__ v)
{
    __shared__ __half vt_s[Dh][72];           // transposed V tile staging
    const int h  = blockIdx.x;
    const int s0 = blockIdx.y * 64;
    const int t  = threadIdx.x;
    const float c = 0.125f * 1.44269504088896340736f;   // D^-0.5 * log2(e)

    #pragma unroll
    for (int i = 0; i < 8; i++) {
        int idx = t + i * 128;                // 0..1023
        int row = idx >> 4, c4 = idx & 15;    // 64 rows x 16 float4-chunks
        size_t g = (size_t)(s0 + row) * (H * Dh) + (size_t)h * Dh + c4 * 4;
        float4 fq = *(const float4*)(q + g);
        float4 fk = *(const float4*)(k + g);
        float4 fv = *(const float4*)(v + g);
        ((__half2*)(qh_g + g))[0] = __floats2half2_rn(fq.x * c, fq.y * c);
        ((__half2*)(qh_g + g))[1] = __floats2half2_rn(fq.z * c, fq.w * c);
        ((__half2*)(kh_g + g))[0] = __floats2half2_rn(fk.x, fk.y);
        ((__half2*)(kh_g + g))[1] = __floats2half2_rn(fk.z, fk.w);
        vt_s[c4 * 4 + 0][row] = __float2half_rn(fv.x);
        vt_s[c4 * 4 + 1][row] = __float2half_rn(fv.y);
        vt_s[c4 * 4 + 2][row] = __float2half_rn(fv.z);
        vt_s[c4 * 4 + 3][row] = __float2half_rn(fv.w);
    }
    __syncthreads();
    #pragma unroll
    for (int i = 0; i < 16; i++) {
        int idx = t + i * 128;                // 0..2047 half2 chunks
        int d = idx >> 5, c2 = idx & 31;
        __half2 val = __halves2half2(vt_s[d][2 * c2], vt_s[d][2 * c2 + 1]);
        *(__half2*)(vth_g + ((size_t)h * Dh + d) * S_LEN + s0 + c2 * 2) = val;
    }
}

// copy one 64x64 K tile + Vt tile (half) -> smem; 4+4 16B chunks per thread
__device__ __forceinline__ void issue_tile(uint32_t kdst, uint32_t vdst,
                                           int k0, int h, int t) {
    #pragma unroll
    for (int i = 0; i < 4; i++) {
        int idx = t + i * NT;                 // 0..511
        int row = idx >> 3, c = idx & 7;      // 64 rows x 8 16B-chunks
        cpa16(kdst + (uint32_t)(row * PH + c * 8) * 2,
              kh_g + (size_t)(k0 + row) * (H * Dh) + (size_t)h * Dh + c * 8);
        cpa16(vdst + (uint32_t)(row * PH + c * 8) * 2,
              vth_g + ((size_t)h * Dh + row) * S_LEN + k0 + c * 8);
    }
    asm volatile("cp.async.commit_group;" ::: "memory");
}

__global__ void __launch_bounds__(NT, 2)
fa_mma_kernel(const int* __restrict__ causal_p, float* __restrict__ out)
{
    extern __shared__ __half smh[];
    uint32_t smb;
    asm("{ .reg .u64 t; cvta.to.shared.u64 t, %1; cvt.u32.u64 %0, t; }"
        : "=r"(smb) : "l"(smh));
    __half* Psh = smh + PSH_OFF;

    const int t    = threadIdx.x;
    const int lane = t & 31;
    const int g    = lane >> 2;
    const int tg   = lane & 3;
    const int h    = blockIdx.x;
    const int qb   = (int)gridDim.y - 1 - (int)blockIdx.y;  // heavy tiles first
    const int causal = *causal_p;
    const int wb   = (t >> 5) * 32;       // warp's 32-row base in CTA tile
    const int q0   = qb * BM;
    const int ktiles = causal ? 2 * (qb + 1) : (S_LEN / BN);

    // ldmatrix.x4 per-lane base offset: matrices {n,k}, {n,k+8}, {n+8,k}, {n+8,k+8}
    const uint32_t lrow  = lane & 7;
    const uint32_t lnoff = (lane >> 4) * 8;         // n offset 0/8
    const uint32_t lkoff = ((lane >> 3) & 1) * 8;   // k offset 0/8
    const uint32_t lbo   = ((lnoff + lrow) * PH + lkoff) * 2;   // bytes

    // ---- stage Q (group 0) and kv tile 0 (group 1)
    #pragma unroll
    for (int i = 0; i < 8; i++) {
        int idx = t + i * NT;                 // 0..1023
        int row = idx >> 3, c = idx & 7;
        cpa16(smb + (uint32_t)(PSH_OFF + row * PH + c * 8) * 2,
              qh_g + (size_t)(q0 + row) * (H * Dh) + (size_t)h * Dh + c * 8);
    }
    asm volatile("cp.async.commit_group;" ::: "memory");
    issue_tile(smb + KH_OFF * 2, smb + VTH_OFF * 2, 0, h, t);

    asm volatile("cp.async.wait_group 1;" ::: "memory");   // Q ready
    __syncthreads();

    // ---- lift Q fragments (m16n8k16 A layout), rows warp-private
    uint32_t qa[2][4][4];                     // [mtile][ktile][frag]
    #pragma unroll
    for (int mt = 0; mt < 2; mt++) {
        int r0 = wb + mt * 16 + g;
        #pragma unroll
        for (int kt = 0; kt < 4; kt++) {
            const __half* p0 = Psh + r0 * PH + kt * 16 + 2 * tg;
            const __half* p1 = Psh + (r0 + 8) * PH + kt * 16 + 2 * tg;
            qa[mt][kt][0] = *(const uint32_t*)p0;
            qa[mt][kt][1] = *(const uint32_t*)p1;
            qa[mt][kt][2] = *(const uint32_t*)(p0 + 8);
            qa[mt][kt][3] = *(const uint32_t*)(p1 + 8);
        }
    }

    float o[2][8][4];
    #pragma unroll
    for (int mt = 0; mt < 2; mt++)
        #pragma unroll
        for (int nt = 0; nt < 8; nt++)
            #pragma unroll
            for (int e = 0; e < 4; e++) o[mt][nt][e] = 0.0f;
    float mrow[4] = {-INFINITY, -INFINITY, -INFINITY, -INFINITY};
    float lrow_[4] = {0.0f, 0.0f, 0.0f, 0.0f};

    for (int kb = 0; kb < ktiles; kb++) {
        const int k0 = kb * BN;
        const int cur = kb & 1;
        const uint32_t kbase = smb + (uint32_t)(KH_OFF + cur * (BN * PH)) * 2 + lbo;
        const uint32_t vbase = smb + (uint32_t)(VTH_OFF + cur * (BN * PH)) * 2 + lbo;

        __syncthreads();   // prev iter's reads of buffer cur^1 done
        if (kb + 1 < ktiles)
            issue_tile(smb + (KH_OFF + (cur ^ 1) * BN * PH) * 2,
                       smb + (VTH_OFF + (cur ^ 1) * BN * PH) * 2,
                       k0 + BN, h, t);
        else
            asm volatile("cp.async.commit_group;" ::: "memory");
        asm volatile("cp.async.wait_group 1;" ::: "memory");
        __syncthreads();   // tile kb visible CTA-wide

        // ---- MMA1: S[32 x 64] = Q @ K^T (ldmatrix.x4 B-fragments)
        float s[2][8][4];
        #pragma unroll
        for (int mt = 0; mt < 2; mt++)
            #pragma unroll
            for (int nt = 0; nt < 8; nt++)
                #pragma unroll
                for (int e = 0; e < 4; e++) s[mt][nt][e] = 0.0f;
        #pragma unroll
        for (int kt = 0; kt < 4; kt++) {
            #pragma unroll
            for (int np = 0; np < 4; np++) {   // n-pair: rows 16np..16np+15
                uint32_t b0a, b1a, b0b, b1b;
                ldsm4(b0a, b1a, b0b, b1b,
                      kbase + (uint32_t)(np * 16 * PH + kt * 16) * 2);
                mma16(s[0][2 * np],     qa[0][kt], b0a, b1a);
                mma16(s[1][2 * np],     qa[1][kt], b0a, b1a);
                mma16(s[0][2 * np + 1], qa[0][kt], b0b, b1b);
                mma16(s[1][2 * np + 1], qa[1][kt], b0b, b1b);
            }
        }

        // ---- causal mask (diagonal tiles only)
        if (causal && kb >= 2 * qb) {
            #pragma unroll
            for (int mt = 0; mt < 2; mt++) {
                int r0 = q0 + wb + mt * 16 + g;
                #pragma unroll
                for (int nt = 0; nt < 8; nt++) {
                    int col = k0 + nt * 8 + 2 * tg;
                    if (col     > r0)     s[mt][nt][0] = -INFINITY;
                    if (col + 1 > r0)     s[mt][nt][1] = -INFINITY;
                    if (col     > r0 + 8) s[mt][nt][2] = -INFINITY;
                    if (col + 1 > r0 + 8) s[mt][nt][3] = -INFINITY;
                }
            }
        }

        // ---- online softmax (4 rows/thread; quad owns a row)
        #pragma unroll
        for (int mt = 0; mt < 2; mt++) {
            #pragma unroll
            for (int hi = 0; hi < 2; hi++) {
                const int ri = mt * 2 + hi;
                float tm = -INFINITY;
                #pragma unroll
                for (int nt = 0; nt < 8; nt++)
                    tm = fmaxf(tm, fmaxf(s[mt][nt][hi * 2], s[mt][nt][hi * 2 + 1]));
                tm = fmaxf(tm, __shfl_xor_sync(0xffffffffu, tm, 1));
                tm = fmaxf(tm, __shfl_xor_sync(0xffffffffu, tm, 2));
                float nm   = fmaxf(mrow[ri], tm);
                float corr = ex2(mrow[ri] - nm);     // first tile: -inf -> 0
                mrow[ri] = nm;
                float ls = 0.0f;
                #pragma unroll
                for (int nt = 0; nt < 8; nt++) {
                    float e0 = ex2(s[mt][nt][hi * 2]     - nm);
                    float e1 = ex2(s[mt][nt][hi * 2 + 1] - nm);
                    s[mt][nt][hi * 2]     = e0;
                    s[mt][nt][hi * 2 + 1] = e1;
                    ls += e0 + e1;
                    o[mt][nt][hi * 2]     *= corr;
                    o[mt][nt][hi * 2 + 1] *= corr;
                }
                lrow_[ri] = lrow_[ri] * corr + ls;
            }
        }

        // ---- MMA2: O += P[32x64] @ V[64x64], P from registers
        // (m16n8k16 C-fragment == A-fragment layout)
        #pragma unroll
        for (int kt = 0; kt < 4; kt++) {
            uint32_t pa[2][4];
            #pragma unroll
            for (int mt = 0; mt < 2; mt++) {
                pa[mt][0] = h2(s[mt][2 * kt][0],     s[mt][2 * kt][1]);
                pa[mt][1] = h2(s[mt][2 * kt][2],     s[mt][2 * kt][3]);
                pa[mt][2] = h2(s[mt][2 * kt + 1][0], s[mt][2 * kt + 1][1]);
                pa[mt][3] = h2(s[mt][2 * kt + 1][2], s[mt][2 * kt + 1][3]);
            }
            #pragma unroll
            for (int np = 0; np < 4; np++) {   // d-pair: rows 16np..16np+15
                uint32_t b0a, b1a, b0b, b1b;
                ldsm4(b0a, b1a, b0b, b1b,
                      vbase + (uint32_t)(np * 16 * PH + kt * 16) * 2);
                mma16(o[0][2 * np],     pa[0], b0a, b1a);
                mma16(o[1][2 * np],     pa[1], b0a, b1a);
                mma16(o[0][2 * np + 1], pa[0], b0b, b1b);
                mma16(o[1][2 * np + 1], pa[1], b0b, b1b);
            }
        }
    }

    // ---- finalize: row-sum across quad, normalize, store
    #pragma unroll
    for (int ri = 0; ri < 4; ri++) {
        lrow_[ri] += __shfl_xor_sync(0xffffffffu, lrow_[ri], 1);
        lrow_[ri] += __shfl_xor_sync(0xffffffffu, lrow_[ri], 2);
    }
    #pragma unroll
    for (int mt = 0; mt < 2; mt++) {
        #pragma unroll
        for (int hi = 0; hi < 2; hi++) {
            const int ri = mt * 2 + hi;
            const float inv = 1.0f / lrow_[ri];
            const int rg = q0 + wb + mt * 16 + g + hi * 8;
            float* op = out + (size_t)rg * (H * Dh) + (size_t)h * Dh;
            #pragma unroll
            for (int nt = 0; nt < 8; nt++) {
                float2 f2;
                f2.x = o[mt][nt][hi * 2]     * inv;
                f2.y = o[mt][nt][hi * 2 + 1] * inv;
                *(float2*)(op + nt * 8 + 2 * tg) = f2;
            }
        }
    }
}

extern "C" void kernel_launch(void* const* d_in, const int* in_sizes, int n_in,
                              void* d_out, int out_size)
{
    const float* q = (const float*)d_in[0];
    const float* k = (const float*)d_in[1];
    const float* v = (const float*)d_in[2];
    const int* causal = (const int*)d_in[3];
    float* out = (float*)d_out;

    dim3 cgrid(H, S_LEN / 64);   // (16, 64)
    cvt_kernel<<<cgrid, 128>>>(q, k, v);

    cudaFuncSetAttribute(fa_mma_kernel,
                         cudaFuncAttributeMaxDynamicSharedMemorySize, SMEM_BYTES);
    dim3 grid(H, S_LEN / BM);    // (16, 32)
    fa_mma_kernel<<<grid, NT, SMEM_BYTES>>>(causal, out);
}

// round 12
// speedup vs baseline: 1.6672x; 1.0531x over previous
#include <cuda_runtime.h>
#include <cuda_fp16.h>
#include <math.h>
#include <stdint.h>

// FlashAttention fwd, causal, fp32 I/O, fp16 mma.sync (m16n8k16), sm_103.
// B=1, S=4096, H=16, D=64. Layout [s,h,d]: d contiguous, s stride 1024.
//
// Pre-pass converts once: qh = half(q*scale), kh = half(k), vth = half(V^T).
// Main kernel: CTA = (head, 128 q rows), 4 warps x 32 rows, BN=64 kv tiles
// double-buffered via cp.async. P stays in registers (C-frag == A-frag).
// K/V B-fragments via ldmatrix.x4. Row-sum l computed by the PV MMA against
// a static ones-row appended to Vt. exp via ex2.approx.f16x2.

constexpr int S_LEN = 4096;
constexpr int H     = 16;
constexpr int Dh    = 64;
constexpr int BM    = 128;
constexpr int BN    = 64;
constexpr int NT    = 128;
constexpr int PH    = 72;        // smem pitch in halves (conflict-free ldsm)
constexpr int VROWS = 72;        // Vt rows: 64 data + ones row (64) + 7 pad

// smem offsets in halves
constexpr int KH_OFF  = 0;                       // 2 x 64x72
constexpr int VTH_OFF = 2 * BN * PH;             // 2 x 72x72
constexpr int V_BUF   = VROWS * PH;
constexpr int PSH_OFF = VTH_OFF + 2 * V_BUF;     // 128x72 (Q staging only)
constexpr int SMEM_H  = PSH_OFF + BM * PH;
constexpr int SMEM_BYTES = SMEM_H * 2;           // 57600 B -> 2 CTAs/SM

// one-time converted operands
__device__ __half qh_g[S_LEN * H * Dh];       // [s][h][d], pre-scaled
__device__ __half kh_g[S_LEN * H * Dh];       // [s][h][d]
__device__ __half vth_g[H * Dh * S_LEN];      // [h][d][s]  (V transposed)

__device__ __forceinline__ float ex2(float x) {
    float y;
    asm("ex2.approx.f32 %0, %1;" : "=f"(y) : "f"(x));
    return y;
}
__device__ __forceinline__ uint32_t ex2h2(uint32_t x) {
    uint32_t y;
    asm("ex2.approx.f16x2 %0, %1;" : "=r"(y) : "r"(x));
    return y;
}
__device__ __forceinline__ void mma16(float* d, const uint32_t* a,
                                      uint32_t b0, uint32_t b1) {
    asm volatile(
        "mma.sync.aligned.m16n8k16.row.col.f32.f16.f16.f32 "
        "{%0,%1,%2,%3}, {%4,%5,%6,%7}, {%8,%9}, {%0,%1,%2,%3};"
        : "+f"(d[0]), "+f"(d[1]), "+f"(d[2]), "+f"(d[3])
        : "r"(a[0]), "r"(a[1]), "r"(a[2]), "r"(a[3]), "r"(b0), "r"(b1));
}
__device__ __forceinline__ void ldsm4(uint32_t& r0, uint32_t& r1,
                                      uint32_t& r2, uint32_t& r3, uint32_t a) {
    asm volatile("ldmatrix.sync.aligned.m8n8.x4.shared.b16 {%0,%1,%2,%3}, [%4];"
                 : "=r"(r0), "=r"(r1), "=r"(r2), "=r"(r3) : "r"(a));
}
__device__ __forceinline__ void ldsm2(uint32_t& r0, uint32_t& r1, uint32_t a) {
    asm volatile("ldmatrix.sync.aligned.m8n8.x2.shared.b16 {%0,%1}, [%2];"
                 : "=r"(r0), "=r"(r1) : "r"(a));
}
__device__ __forceinline__ void cpa16(uint32_t dst, const void* src) {
    asm volatile("cp.async.cg.shared.global [%0], [%1], 16;"
                 :: "r"(dst), "l"(src) : "memory");
}
__device__ __forceinline__ uint32_t h2(float a, float b) {
    __half2 v = __floats2half2_rn(a, b);
    return *(uint32_t*)&v;
}

// ---------------- pre-pass: fp32 -> fp16 (+scale Q, transpose V) ----------
__global__ void __launch_bounds__(128)
cvt_kernel(const float* __restrict__ q, const float* __restrict__ k,
           const float* __restrict__ v)
{
    __shared__ __half vt_s[Dh][72];           // transposed V tile staging
    const int h  = blockIdx.x;
    const int s0 = blockIdx.y * 64;
    const int t  = threadIdx.x;
    const float c = 0.125f * 1.44269504088896340736f;   // D^-0.5 * log2(e)

    #pragma unroll
    for (int i = 0; i < 8; i++) {
        int idx = t + i * 128;                // 0..1023
        int row = idx >> 4, c4 = idx & 15;    // 64 rows x 16 float4-chunks
        size_t g = (size_t)(s0 + row) * (H * Dh) + (size_t)h * Dh + c4 * 4;
        float4 fq = *(const float4*)(q + g);
        float4 fk = *(const float4*)(k + g);
        float4 fv = *(const float4*)(v + g);
        ((__half2*)(qh_g + g))[0] = __floats2half2_rn(fq.x * c, fq.y * c);
        ((__half2*)(qh_g + g))[1] = __floats2half2_rn(fq.z * c, fq.w * c);
        ((__half2*)(kh_g + g))[0] = __floats2half2_rn(fk.x, fk.y);
        ((__half2*)(kh_g + g))[1] = __floats2half2_rn(fk.z, fk.w);
        vt_s[c4 * 4 + 0][row] = __float2half_rn(fv.x);
        vt_s[c4 * 4 + 1][row] = __float2half_rn(fv.y);
        vt_s[c4 * 4 + 2][row] = __float2half_rn(fv.z);
        vt_s[c4 * 4 + 3][row] = __float2half_rn(fv.w);
    }
    __syncthreads();
    #pragma unroll
    for (int i = 0; i < 16; i++) {
        int idx = t + i * 128;                // 0..2047 half2 chunks
        int d = idx >> 5, c2 = idx & 31;
        __half2 val = __halves2half2(vt_s[d][2 * c2], vt_s[d][2 * c2 + 1]);
        *(__half2*)(vth_g + ((size_t)h * Dh + d) * S_LEN + s0 + c2 * 2) = val;
    }
}

// copy one 64x64 K tile + Vt tile (half) -> smem; 4+4 16B chunks per thread
__device__ __forceinline__ void issue_tile(uint32_t kdst, uint32_t vdst,
                                           int k0, int h, int t) {
    #pragma unroll
    for (int i = 0; i < 4; i++) {
        int idx = t + i * NT;                 // 0..511
        int row = idx >> 3, c = idx & 7;      // 64 rows x 8 16B-chunks
        cpa16(kdst + (uint32_t)(row * PH + c * 8) * 2,
              kh_g + (size_t)(k0 + row) * (H * Dh) + (size_t)h * Dh + c * 8);
        cpa16(vdst + (uint32_t)(row * PH + c * 8) * 2,
              vth_g + ((size_t)h * Dh + row) * S_LEN + k0 + c * 8);
    }
    asm volatile("cp.async.commit_group;" ::: "memory");
}

__global__ void __launch_bounds__(NT, 2)
fa_mma_kernel(const int* __restrict__ causal_p, float* __restrict__ out)
{
    extern __shared__ __half smh[];
    uint32_t smb;
    asm("{ .reg .u64 t; cvta.to.shared.u64 t, %1; cvt.u32.u64 %0, t; }"
        : "=r"(smb) : "l"(smh));
    __half* Psh = smh + PSH_OFF;

    const int t    = threadIdx.x;
    const int lane = t & 31;
    const int g    = lane >> 2;
    const int tg   = lane & 3;
    const int h    = blockIdx.x;
    const int qb   = (int)gridDim.y - 1 - (int)blockIdx.y;  // heavy tiles first
    const int causal = *causal_p;
    const int wb   = (t >> 5) * 32;       // warp's 32-row base in CTA tile
    const int q0   = qb * BM;
    const int ktiles = causal ? 2 * (qb + 1) : (S_LEN / BN);

    // ldmatrix.x4 per-lane base: matrices {n,k},{n,k+8},{n+8,k},{n+8,k+8}
    const uint32_t lrw   = lane & 7;
    const uint32_t lnoff = (lane >> 4) * 8;
    const uint32_t lkoff = ((lane >> 3) & 1) * 8;
    const uint32_t lbo   = ((lnoff + lrw) * PH + lkoff) * 2;
    // ldmatrix.x2 per-lane base (lanes 0-15 meaningful): {k},{k+8}
    const uint32_t lbo2  = (lrw * PH + lkoff) * 2;

    // ---- static ones-row for the l-column (Vt row 64, both buffers)
    if (t < 64) {
        smh[VTH_OFF + 0 * V_BUF + 64 * PH + t] = __float2half(1.0f);
        smh[VTH_OFF + 1 * V_BUF + 64 * PH + t] = __float2half(1.0f);
    }

    // ---- stage Q (group 0) and kv tile 0 (group 1)
    #pragma unroll
    for (int i = 0; i < 8; i++) {
        int idx = t + i * NT;                 // 0..1023
        int row = idx >> 3, c = idx & 7;
        cpa16(smb + (uint32_t)(PSH_OFF + row * PH + c * 8) * 2,
              qh_g + (size_t)(q0 + row) * (H * Dh) + (size_t)h * Dh + c * 8);
    }
    asm volatile("cp.async.commit_group;" ::: "memory");
    issue_tile(smb + KH_OFF * 2, smb + VTH_OFF * 2, 0, h, t);

    asm volatile("cp.async.wait_group 1;" ::: "memory");   // Q ready
    __syncthreads();

    // ---- lift Q fragments (m16n8k16 A layout), rows warp-private
    uint32_t qa[2][4][4];                     // [mtile][ktile][frag]
    #pragma unroll
    for (int mt = 0; mt < 2; mt++) {
        int r0 = wb + mt * 16 + g;
        #pragma unroll
        for (int kt = 0; kt < 4; kt++) {
            const __half* p0 = Psh + r0 * PH + kt * 16 + 2 * tg;
            const __half* p1 = Psh + (r0 + 8) * PH + kt * 16 + 2 * tg;
            qa[mt][kt][0] = *(const uint32_t*)p0;
            qa[mt][kt][1] = *(const uint32_t*)p1;
            qa[mt][kt][2] = *(const uint32_t*)(p0 + 8);
            qa[mt][kt][3] = *(const uint32_t*)(p1 + 8);
        }
    }

    float o[2][8][4];
    #pragma unroll
    for (int mt = 0; mt < 2; mt++)
        #pragma unroll
        for (int nt = 0; nt < 8; nt++)
            #pragma unroll
            for (int e = 0; e < 4; e++) o[mt][nt][e] = 0.0f;
    float o_l[2][4];                          // l accumulator (col 64; tg=0)
    #pragma unroll
    for (int mt = 0; mt < 2; mt++)
        #pragma unroll
        for (int e = 0; e < 4; e++) o_l[mt][e] = 0.0f;
    float mrow[4] = {-INFINITY, -INFINITY, -INFINITY, -INFINITY};

    for (int kb = 0; kb < ktiles; kb++) {
        const int k0 = kb * BN;
        const int cur = kb & 1;
        const uint32_t kbase = smb + (uint32_t)(KH_OFF + cur * (BN * PH)) * 2 + lbo;
        const uint32_t vbase = smb + (uint32_t)(VTH_OFF + cur * V_BUF) * 2 + lbo;
        const uint32_t vones = smb + (uint32_t)(VTH_OFF + cur * V_BUF + 64 * PH) * 2 + lbo2;

        __syncthreads();   // prev iter's reads of buffer cur^1 done
        if (kb + 1 < ktiles)
            issue_tile(smb + (KH_OFF + (cur ^ 1) * BN * PH) * 2,
                       smb + (VTH_OFF + (cur ^ 1) * V_BUF) * 2,
                       k0 + BN, h, t);
        else
            asm volatile("cp.async.commit_group;" ::: "memory");
        asm volatile("cp.async.wait_group 1;" ::: "memory");
        __syncthreads();   // tile kb visible CTA-wide

        // ---- MMA1: S[32 x 64] = Q @ K^T (ldmatrix.x4 B-fragments)
        float s[2][8][4];
        #pragma unroll
        for (int mt = 0; mt < 2; mt++)
            #pragma unroll
            for (int nt = 0; nt < 8; nt++)
                #pragma unroll
                for (int e = 0; e < 4; e++) s[mt][nt][e] = 0.0f;
        #pragma unroll
        for (int kt = 0; kt < 4; kt++) {
            #pragma unroll
            for (int np = 0; np < 4; np++) {
                uint32_t b0a, b1a, b0b, b1b;
                ldsm4(b0a, b1a, b0b, b1b,
                      kbase + (uint32_t)(np * 16 * PH + kt * 16) * 2);
                mma16(s[0][2 * np],     qa[0][kt], b0a, b1a);
                mma16(s[1][2 * np],     qa[1][kt], b0a, b1a);
                mma16(s[0][2 * np + 1], qa[0][kt], b0b, b1b);
                mma16(s[1][2 * np + 1], qa[1][kt], b0b, b1b);
            }
        }

        // ---- causal mask (diagonal tiles only)
        if (causal && kb >= 2 * qb) {
            #pragma unroll
            for (int mt = 0; mt < 2; mt++) {
                int r0 = q0 + wb + mt * 16 + g;
                #pragma unroll
                for (int nt = 0; nt < 8; nt++) {
                    int col = k0 + nt * 8 + 2 * tg;
                    if (col     > r0)     s[mt][nt][0] = -INFINITY;
                    if (col + 1 > r0)     s[mt][nt][1] = -INFINITY;
                    if (col     > r0 + 8) s[mt][nt][2] = -INFINITY;
                    if (col + 1 > r0 + 8) s[mt][nt][3] = -INFINITY;
                }
            }
        }

        // ---- online softmax -> P fragments (half2) directly
        uint32_t ph[2][8][2];                 // [mt][nt][hi]: exp'd half2 pairs
        #pragma unroll
        for (int mt = 0; mt < 2; mt++) {
            #pragma unroll
            for (int hi = 0; hi < 2; hi++) {
                const int ri = mt * 2 + hi;
                float tm = -INFINITY;
                #pragma unroll
                for (int nt = 0; nt < 8; nt++)
                    tm = fmaxf(tm, fmaxf(s[mt][nt][hi * 2], s[mt][nt][hi * 2 + 1]));
                tm = fmaxf(tm, __shfl_xor_sync(0xffffffffu, tm, 1));
                tm = fmaxf(tm, __shfl_xor_sync(0xffffffffu, tm, 2));
                float nm   = fmaxf(mrow[ri], tm);
                float corr = ex2(mrow[ri] - nm);     // first tile: -inf -> 0
                mrow[ri] = nm;
                #pragma unroll
                for (int nt = 0; nt < 8; nt++) {
                    ph[mt][nt][hi] = ex2h2(h2(s[mt][nt][hi * 2]     - nm,
                                              s[mt][nt][hi * 2 + 1] - nm));
                    o[mt][nt][hi * 2]     *= corr;
                    o[mt][nt][hi * 2 + 1] *= corr;
                }
                o_l[mt][hi * 2]     *= corr;
                o_l[mt][hi * 2 + 1] *= corr;
            }
        }

        // ---- MMA2: O += P @ V, plus l column against the ones-row
        #pragma unroll
        for (int kt = 0; kt < 4; kt++) {
            uint32_t pa[2][4];
            #pragma unroll
            for (int mt = 0; mt < 2; mt++) {
                pa[mt][0] = ph[mt][2 * kt][0];
                pa[mt][1] = ph[mt][2 * kt][1];
                pa[mt][2] = ph[mt][2 * kt + 1][0];
                pa[mt][3] = ph[mt][2 * kt + 1][1];
            }
            #pragma unroll
            for (int np = 0; np < 4; np++) {
                uint32_t b0a, b1a, b0b, b1b;
                ldsm4(b0a, b1a, b0b, b1b,
                      vbase + (uint32_t)(np * 16 * PH + kt * 16) * 2);
                mma16(o[0][2 * np],     pa[0], b0a, b1a);
                mma16(o[1][2 * np],     pa[1], b0a, b1a);
                mma16(o[0][2 * np + 1], pa[0], b0b, b1b);
                mma16(o[1][2 * np + 1], pa[1], b0b, b1b);
            }
            uint32_t l0, l1;                  // ones-row block (rows 64-71)
            ldsm2(l0, l1, vones + (uint32_t)(kt * 16) * 2);
            mma16(o_l[0], pa[0], l0, l1);
            mma16(o_l[1], pa[1], l0, l1);
        }
    }

    // ---- finalize: l lives in tg=0 lane (col 64): broadcast, normalize, store
    #pragma unroll
    for (int mt = 0; mt < 2; mt++) {
        #pragma unroll
        for (int hi = 0; hi < 2; hi++) {
            const float lv = __shfl_sync(0xffffffffu, o_l[mt][hi * 2],
                                         lane & ~3);
            const float inv = 1.0f / lv;
            const int rg = q0 + wb + mt * 16 + g + hi * 8;
            float* op = out + (size_t)rg * (H * Dh) + (size_t)h * Dh;
            #pragma unroll
            for (int nt = 0; nt < 8; nt++) {
                float2 f2;
                f2.x = o[mt][nt][hi * 2]     * inv;
                f2.y = o[mt][nt][hi * 2 + 1] * inv;
                *(float2*)(op + nt * 8 + 2 * tg) = f2;
            }
        }
    }
}

extern "C" void kernel_launch(void* const* d_in, const int* in_sizes, int n_in,
                              void* d_out, int out_size)
{
    const float* q = (const float*)d_in[0];
    const float* k = (const float*)d_in[1];
    const float* v = (const float*)d_in[2];
    const int* causal = (const int*)d_in[3];
    float* out = (float*)d_out;

    dim3 cgrid(H, S_LEN / 64);   // (16, 64)
    cvt_kernel<<<cgrid, 128>>>(q, k, v);

    cudaFuncSetAttribute(fa_mma_kernel,
                         cudaFuncAttributeMaxDynamicSharedMemorySize, SMEM_BYTES);
    dim3 grid(H, S_LEN / BM);    // (16, 32)
    fa_mma_kernel<<<grid, NT, SMEM_BYTES>>>(causal, out);
}